// round 15
// baseline (speedup 1.0000x reference)
#include <cuda_runtime.h>
#include <cuda_bf16.h>
#include <cstdint>

#define Bsz  8
#define NF   2048
#define NK   4096
#define CIN  256
#define CKQ  64
#define COUT 256
#define SEQ  (NF + NK)

// ---------------- scratch (__device__ globals; no allocations allowed) -----
__device__ __align__(16) __nv_bfloat16 g_Wq[CKQ * CIN];
__device__ __align__(16) __nv_bfloat16 g_Wkv[(CKQ + COUT) * CIN];
__device__ __align__(16) __nv_bfloat16 g_Q[Bsz * NF * CKQ];        // log2-domain scaled
__device__ __align__(16) __nv_bfloat16 g_K[Bsz * NK * CKQ];
__device__ __align__(16) __nv_bfloat16 g_Vt[Bsz * COUT * NK];      // [b][c][key]
// P: blocked [b][qt][kt][128 rows][64 u32 cols], col = t*16 + nt (fragment-native)
__device__ __align__(16) __nv_bfloat16 g_P[Bsz * NF * NK];         // 128 MB
__device__ __align__(16) float         g_rsumH[2 * Bsz * NF];      // per-kt-half row sums

// 1/sqrt(64) * log2(e): scores land directly in log2 domain -> ex2.approx
#define SCALE_Q 0.180336884f

// =================== helpers =============================================
__device__ __forceinline__ uint32_t smem_u32(const void* p) {
    uint32_t a;
    asm("{ .reg .u64 t; cvta.to.shared.u64 t, %1; cvt.u32.u64 %0, t; }" : "=r"(a) : "l"(p));
    return a;
}
__device__ __forceinline__ float ex2f(float x) {
    float y; asm("ex2.approx.ftz.f32 %0, %1;" : "=f"(y) : "f"(x)); return y;
}
__device__ __forceinline__ unsigned pack_bf2(float lo, float hi) {
    __nv_bfloat162 h = __floats2bfloat162_rn(lo, hi);
    return *reinterpret_cast<unsigned*>(&h);
}
__device__ __forceinline__ void cp16(uint32_t dst, const void* src) {
    asm volatile("cp.async.cg.shared.global [%0], [%1], 16;" :: "r"(dst), "l"(src) : "memory");
}
#define CP_COMMIT() asm volatile("cp.async.commit_group;" ::: "memory")
#define CP_WAIT(n)  asm volatile("cp.async.wait_group %0;" :: "n"(n) : "memory")

// ldmatrix x4: four 8x8 b16 tiles
__device__ __forceinline__ void ldsm_x4(unsigned r[4], uint32_t addr) {
    asm volatile("ldmatrix.sync.aligned.m8n8.x4.shared.b16 {%0,%1,%2,%3}, [%4];"
        : "=r"(r[0]), "=r"(r[1]), "=r"(r[2]), "=r"(r[3]) : "r"(addr));
}

// mma.sync m16n8k16 bf16 -> f32 (sm_80 baseline; family-portable)
__device__ __forceinline__ void mma_bf16(float c[4], const unsigned a[4], const unsigned b0, const unsigned b1) {
    asm volatile(
        "mma.sync.aligned.m16n8k16.row.col.f32.bf16.bf16.f32 "
        "{%0,%1,%2,%3}, {%4,%5,%6,%7}, {%8,%9}, {%0,%1,%2,%3};\n"
        : "+f"(c[0]), "+f"(c[1]), "+f"(c[2]), "+f"(c[3])
        : "r"(a[0]), "r"(a[1]), "r"(a[2]), "r"(a[3]), "r"(b0), "r"(b1));
}
__device__ __forceinline__ void mma_bf16a(float c[4], const unsigned a[4], const unsigned b[2]) {
    mma_bf16(c, a, b[0], b[1]);
}

// ---------------- kernel 0: weight conversion ------------------------------
__global__ void k_convert(const float* __restrict__ Wq, const float* __restrict__ Wk,
                          const float* __restrict__ Wv) {
    int i = blockIdx.x * blockDim.x + threadIdx.x;
    const int n1 = CKQ * CIN;
    const int n2 = (CKQ + COUT) * CIN;
    if (i < n1) g_Wq[i] = __float2bfloat16_rn(Wq[i]);
    if (i < n2) g_Wkv[i] = __float2bfloat16_rn(i < n1 ? Wk[i] : Wv[i - n1]);
}

// ---------------- kernel 1: fused QKV projection + keep-row copy -----------
// 256-row tile per CTA (grid 192), 8 warps x M32. (Unchanged from R14.)
#define AS_STRIDE 264
#define VS_STRIDE 66
#define PROJ_SMEM (256 * AS_STRIDE * 2 + 256 * VS_STRIDE * 2)   // 168960

__global__ __launch_bounds__(256) void k_proj(const float* __restrict__ feat,
                                              const float* __restrict__ bq,
                                              const float* __restrict__ bk,
                                              const float* __restrict__ bv,
                                              float* __restrict__ out) {
    extern __shared__ char smem[];
    __nv_bfloat16* As  = reinterpret_cast<__nv_bfloat16*>(smem);
    __nv_bfloat16* Vsm = reinterpret_cast<__nv_bfloat16*>(smem + 256 * AS_STRIDE * 2);

    const int tid = threadIdx.x;
    const int w = tid >> 5, lane = tid & 31;
    const int g = lane >> 2, t = lane & 3;
    const int m0 = w * 32;

    const int row0 = blockIdx.x * 256;
    const int b = row0 / SEQ;
    const int pos0 = row0 % SEQ;
    const bool is_fill = pos0 < NF;

    if (!is_fill) {
        const float4* src = reinterpret_cast<const float4*>(feat + (size_t)row0 * CIN);
        float4* dst = reinterpret_cast<float4*>(out + (size_t)row0 * CIN);
        for (int i = tid; i < 256 * CIN / 4; i += 256) dst[i] = src[i];
    }

    for (int i = tid; i < 256 * 64; i += 256) {
        const int r = i >> 6, c4 = i & 63;
        float4 v = *reinterpret_cast<const float4*>(&feat[(size_t)(row0 + r) * CIN + c4 * 4]);
        *reinterpret_cast<__nv_bfloat162*>(&As[r * AS_STRIDE + c4 * 4]) = __floats2bfloat162_rn(v.x, v.y);
        *reinterpret_cast<__nv_bfloat162*>(&As[r * AS_STRIDE + c4 * 4 + 2]) = __floats2bfloat162_rn(v.z, v.w);
    }
    __syncthreads();

    const int nchunks = is_fill ? 1 : 5;
    for (int nc = 0; nc < nchunks; nc++) {
        const __nv_bfloat16* W = is_fill ? g_Wq : g_Wkv;
        const int nbase = is_fill ? 0 : nc * 64;

        float acc[2][8][4];
#pragma unroll
        for (int mt = 0; mt < 2; mt++)
#pragma unroll
            for (int nt = 0; nt < 8; nt++) {
                acc[mt][nt][0] = acc[mt][nt][1] = acc[mt][nt][2] = acc[mt][nt][3] = 0.f;
            }

#pragma unroll
        for (int kt = 0; kt < 16; kt++) {
            const int k0 = kt * 16;
            unsigned a[2][4];
#pragma unroll
            for (int mt = 0; mt < 2; mt++) {
                const int r0 = m0 + mt * 16 + g;
                a[mt][0] = *reinterpret_cast<const unsigned*>(&As[r0       * AS_STRIDE + k0 + 2 * t]);
                a[mt][1] = *reinterpret_cast<const unsigned*>(&As[(r0 + 8) * AS_STRIDE + k0 + 2 * t]);
                a[mt][2] = *reinterpret_cast<const unsigned*>(&As[r0       * AS_STRIDE + k0 + 8 + 2 * t]);
                a[mt][3] = *reinterpret_cast<const unsigned*>(&As[(r0 + 8) * AS_STRIDE + k0 + 8 + 2 * t]);
            }
#pragma unroll
            for (int nt = 0; nt < 8; nt++) {
                const int n = nbase + nt * 8 + g;
                unsigned bf[2];
                bf[0] = *reinterpret_cast<const unsigned*>(&W[n * CIN + k0 + 2 * t]);
                bf[1] = *reinterpret_cast<const unsigned*>(&W[n * CIN + k0 + 8 + 2 * t]);
                mma_bf16a(acc[0][nt], a[0], bf);
                mma_bf16a(acc[1][nt], a[1], bf);
            }
        }

        if (is_fill) {
#pragma unroll
            for (int mt = 0; mt < 2; mt++) {
                const int qrow = b * NF + pos0 + m0 + mt * 16 + g;
#pragma unroll
                for (int nt = 0; nt < 8; nt++) {
                    const int col = nt * 8 + 2 * t;
                    const float b0v = bq[col], b1v = bq[col + 1];
                    *reinterpret_cast<unsigned*>(&g_Q[(size_t)qrow * CKQ + col]) =
                        pack_bf2((acc[mt][nt][0] + b0v) * SCALE_Q, (acc[mt][nt][1] + b1v) * SCALE_Q);
                    *reinterpret_cast<unsigned*>(&g_Q[(size_t)(qrow + 8) * CKQ + col]) =
                        pack_bf2((acc[mt][nt][2] + b0v) * SCALE_Q, (acc[mt][nt][3] + b1v) * SCALE_Q);
                }
            }
        } else if (nc == 0) {
#pragma unroll
            for (int mt = 0; mt < 2; mt++) {
                const int krow = b * NK + (pos0 - NF) + m0 + mt * 16 + g;
#pragma unroll
                for (int nt = 0; nt < 8; nt++) {
                    const int col = nt * 8 + 2 * t;
                    const float b0v = bk[col], b1v = bk[col + 1];
                    *reinterpret_cast<unsigned*>(&g_K[(size_t)krow * CKQ + col]) =
                        pack_bf2(acc[mt][nt][0] + b0v, acc[mt][nt][1] + b1v);
                    *reinterpret_cast<unsigned*>(&g_K[(size_t)(krow + 8) * CKQ + col]) =
                        pack_bf2(acc[mt][nt][2] + b0v, acc[mt][nt][3] + b1v);
                }
            }
        } else {
#pragma unroll
            for (int mt = 0; mt < 2; mt++) {
                const int r0 = m0 + mt * 16 + g;
#pragma unroll
                for (int nt = 0; nt < 8; nt++) {
                    const int col = nt * 8 + 2 * t;
                    const int nglob = (nc - 1) * 64 + col;
                    const float b0v = bv[nglob], b1v = bv[nglob + 1];
                    *reinterpret_cast<unsigned*>(&Vsm[r0       * VS_STRIDE + col]) =
                        pack_bf2(acc[mt][nt][0] + b0v, acc[mt][nt][1] + b1v);
                    *reinterpret_cast<unsigned*>(&Vsm[(r0 + 8) * VS_STRIDE + col]) =
                        pack_bf2(acc[mt][nt][2] + b0v, acc[mt][nt][3] + b1v);
                }
            }
            __syncthreads();
            const int key0 = pos0 - NF;
            for (int i = tid; i < 64 * 128; i += 256) {
                const int n = i >> 7;
                const int kp = i & 127;
                __nv_bfloat162 h;
                h.x = Vsm[(2 * kp)     * VS_STRIDE + n];
                h.y = Vsm[(2 * kp + 1) * VS_STRIDE + n];
                const int nglob = (nc - 1) * 64 + n;
                *reinterpret_cast<__nv_bfloat162*>(
                    &g_Vt[((size_t)(b * COUT + nglob)) * NK + key0 + 2 * kp]) = h;
            }
            __syncthreads();
        }
    }
}

// ---------------- kernel 2: scores + exp -> unnormalized P -----------------
// Each CTA: 128 q rows x HALF the KV range (16 tiles). grid = 256.
// 4-stage/1-barrier cp.async pipeline; P stored fragment-native with STG.128.
#define SC_QS 72
#define SC_KS 72
#define SC_SMK(s) (18432 + (s) * 18432)
#define SCORE_SMEM (5 * 18432)     // Q + 4 K stages = 92160

__global__ __launch_bounds__(256, 2) void k_score() {
    extern __shared__ char smem[];
    const uint32_t sb = smem_u32(smem);
    const int tid = threadIdx.x;
    const int w = tid >> 5, lane = tid & 31;
    const int g = lane >> 2, t = lane & 3;
    const int m0 = w * 16;
    const int b  = blockIdx.x >> 5;
    const int qt = (blockIdx.x >> 1) & 15;
    const int h  = blockIdx.x & 1;
    const int q0 = qt * 128;
    const int kt0 = h * 16;

    const int bRow = (lane & 7) + ((lane >> 4) & 1) * 8;
    const int bKh  = ((lane >> 3) & 1) * 8;

    const __nv_bfloat16* gK = &g_K[(size_t)(b * NK) * CKQ];

    // stage Q tile
    for (int i = tid; i < 128 * 8; i += 256) {
        const int r = i >> 3, c4 = i & 7;
        const uint4 v = *reinterpret_cast<const uint4*>(
            &g_Q[((size_t)(b * NF + q0 + r)) * CKQ + c4 * 8]);
        *reinterpret_cast<uint4*>(smem + (r * SC_QS + c4 * 8) * 2) = v;
    }

    // prefetch K tiles kt0 .. kt0+2 into stages 0..2
#pragma unroll
    for (int pre = 0; pre < 3; pre++) {
        const uint32_t kb = sb + SC_SMK(pre);
        for (int i = tid; i < 1024; i += 256) {
            const int r = i >> 3, c = i & 7;
            cp16(kb + (r * SC_KS + c * 8) * 2, gK + (size_t)((kt0 + pre) * 128 + r) * CKQ + c * 8);
        }
        CP_COMMIT();
    }
    __syncthreads();

    const __nv_bfloat16* Qs = reinterpret_cast<const __nv_bfloat16*>(smem);
    unsigned qf[4][4];
#pragma unroll
    for (int j = 0; j < 4; j++) {
        const int k0 = j * 16;
        qf[j][0] = *reinterpret_cast<const unsigned*>(&Qs[(m0 + g)     * SC_QS + k0 + 2 * t]);
        qf[j][1] = *reinterpret_cast<const unsigned*>(&Qs[(m0 + g + 8) * SC_QS + k0 + 2 * t]);
        qf[j][2] = *reinterpret_cast<const unsigned*>(&Qs[(m0 + g)     * SC_QS + k0 + 8 + 2 * t]);
        qf[j][3] = *reinterpret_cast<const unsigned*>(&Qs[(m0 + g + 8) * SC_QS + k0 + 8 + 2 * t]);
    }

    float rsum0 = 0.f, rsum1 = 0.f;
    uint32_t* pbase = reinterpret_cast<uint32_t*>(g_P) + ((size_t)(b * 16 + qt)) * 32 * 8192;
    const int r0 = m0 + g, r1 = r0 + 8;

    for (int i = 0; i < 16; i++) {
        const int kt = kt0 + i;
        const int s = i & 3;
        const uint32_t ksb = sb + SC_SMK(s);

        CP_WAIT(2);
        __syncthreads();

        // prefetch tile kt+3 into stage (i+3)&3 (its reads finished at i-1)
        if (i + 3 < 16) {
            const uint32_t nb = sb + SC_SMK((i + 3) & 3);
            for (int ii = tid; ii < 1024; ii += 256) {
                const int r = ii >> 3, c = ii & 7;
                cp16(nb + (r * SC_KS + c * 8) * 2, gK + (size_t)((kt + 3) * 128 + r) * CKQ + c * 8);
            }
        }
        CP_COMMIT();

        float sv[16][4];
#pragma unroll
        for (int nt = 0; nt < 16; nt++) { sv[nt][0] = sv[nt][1] = sv[nt][2] = sv[nt][3] = 0.f; }
#pragma unroll
        for (int j = 0; j < 4; j++) {
            const int k0 = j * 16;
#pragma unroll
            for (int np = 0; np < 8; np++) {
                unsigned bb[4];
                ldsm_x4(bb, ksb + (uint32_t)((np * 16 + bRow) * SC_KS + k0 + bKh) * 2);
                mma_bf16(sv[2 * np],     qf[j], bb[0], bb[1]);
                mma_bf16(sv[2 * np + 1], qf[j], bb[2], bb[3]);
            }
        }

        // exp (log2 domain), row sums; store fragment-native: col = t*16 + nt
        uint32_t* pb = pbase + (size_t)kt * 8192;
#pragma unroll
        for (int j = 0; j < 4; j++) {
            uint32_t w0[4], w1[4];
#pragma unroll
            for (int e = 0; e < 4; e++) {
                const int nt = 4 * j + e;
                const float p0 = ex2f(sv[nt][0]);
                const float p1 = ex2f(sv[nt][1]);
                const float p2 = ex2f(sv[nt][2]);
                const float p3 = ex2f(sv[nt][3]);
                rsum0 += p0 + p1;
                rsum1 += p2 + p3;
                w0[e] = pack_bf2(p0, p1);
                w1[e] = pack_bf2(p2, p3);
            }
            *reinterpret_cast<uint4*>(&pb[r0 * 64 + t * 16 + 4 * j]) =
                *reinterpret_cast<const uint4*>(w0);
            *reinterpret_cast<uint4*>(&pb[r1 * 64 + t * 16 + 4 * j]) =
                *reinterpret_cast<const uint4*>(w1);
        }
    }

    // quad-reduce partial row sums, lane t==0 writes this half's sums
    rsum0 += __shfl_xor_sync(0xffffffffu, rsum0, 1);
    rsum0 += __shfl_xor_sync(0xffffffffu, rsum0, 2);
    rsum1 += __shfl_xor_sync(0xffffffffu, rsum1, 1);
    rsum1 += __shfl_xor_sync(0xffffffffu, rsum1, 2);
    if (t == 0) {
        g_rsumH[h * (Bsz * NF) + b * NF + q0 + m0 + g]     = rsum0;
        g_rsumH[h * (Bsz * NF) + b * NF + q0 + m0 + g + 8] = rsum1;
    }
}

// ---------------- kernel 3: O = P @ V, scaled by 1/rsum --------------------
// CTA: 128 q x 128 out channels, 8 warps (4M x 2N), M32N64/warp.
// A (P) loaded DIRECTLY into fragment regs via LDG.128 (fragment-native layout).
// B (V) via 4-stage/1-barrier cp.async + ldmatrix. K-step 64.
#define PV_BST 18432                      // one B stage: 128 rows x 144B
#define PV_SMEM (4 * PV_BST)              // 73728

__global__ __launch_bounds__(256, 2) void k_pv(float* __restrict__ out) {
    extern __shared__ char smem[];
    const uint32_t sb = smem_u32(smem);
    const int tid = threadIdx.x;
    const int w = tid >> 5, lane = tid & 31;
    const int g = lane >> 2, t = lane & 3;
    const int mw = w & 3, nw = w >> 2;          // 4 x 2 warp grid
    const int mbase = mw * 32, nbase = nw * 64;

    const int bRow = (lane & 7) + ((lane >> 4) & 1) * 8;
    const int bKh  = ((lane >> 3) & 1) * 8;

    const int b  = blockIdx.x >> 5;
    const int qt = (blockIdx.x >> 1) & 15;
    const int nh = blockIdx.x & 1;
    const int q0 = qt * 128;

    const uint32_t* gPu = reinterpret_cast<const uint32_t*>(g_P) + ((size_t)(b * 16 + qt)) * 32 * 8192;
    const __nv_bfloat16* gV = &g_Vt[((size_t)(b * COUT + nh * 128)) * NK];

    // prefetch B (V) for ks = 0..2 into stages 0..2
#pragma unroll
    for (int pre = 0; pre < 3; pre++) {
        const uint32_t bb = sb + pre * PV_BST;
        for (int i = tid; i < 1024; i += 256) {
            const int r = i >> 3, c = i & 7;
            cp16(bb + r * 144 + c * 16, gV + (size_t)r * NK + pre * 64 + c * 8);
        }
        CP_COMMIT();
    }

    float acc[2][8][4];
#pragma unroll
    for (int mt = 0; mt < 2; mt++)
#pragma unroll
        for (int nt = 0; nt < 8; nt++) {
            acc[mt][nt][0] = acc[mt][nt][1] = acc[mt][nt][2] = acc[mt][nt][3] = 0.f;
        }

    for (int ks = 0; ks < 64; ks++) {           // 64 K-steps of 64 keys
        const int s = ks & 3;
        const int kt = ks >> 1, half = ks & 1;

        // A fragments: direct LDG.128 from fragment-native P (no smem).
        // Issued before the wait/barrier so L2 latency hides under them.
        unsigned aF[2][2][8];
        const uint32_t* pA = gPu + (size_t)kt * 8192 + t * 16 + half * 8;
#pragma unroll
        for (int mt = 0; mt < 2; mt++) {
            const int r0 = mbase + mt * 16 + g;
            *reinterpret_cast<uint4*>(&aF[mt][0][0]) = *reinterpret_cast<const uint4*>(pA + r0 * 64);
            *reinterpret_cast<uint4*>(&aF[mt][0][4]) = *reinterpret_cast<const uint4*>(pA + r0 * 64 + 4);
            *reinterpret_cast<uint4*>(&aF[mt][1][0]) = *reinterpret_cast<const uint4*>(pA + (r0 + 8) * 64);
            *reinterpret_cast<uint4*>(&aF[mt][1][4]) = *reinterpret_cast<const uint4*>(pA + (r0 + 8) * 64 + 4);
        }

        CP_WAIT(2);
        __syncthreads();

        // prefetch B for ks+3 into stage (ks+3)&3 (reads finished at ks-1)
        if (ks + 3 < 64) {
            const int tn = ks + 3;
            const uint32_t bb = sb + ((ks + 3) & 3) * PV_BST;
            for (int i = tid; i < 1024; i += 256) {
                const int r = i >> 3, c = i & 7;
                cp16(bb + r * 144 + c * 16, gV + (size_t)r * NK + tn * 64 + c * 8);
            }
        }
        CP_COMMIT();

        const uint32_t bB = sb + s * PV_BST;
#pragma unroll
        for (int kk = 0; kk < 4; kk++) {
            const int k0 = kk * 16;
            unsigned a0[4] = { aF[0][0][2 * kk], aF[0][1][2 * kk],
                               aF[0][0][2 * kk + 1], aF[0][1][2 * kk + 1] };
            unsigned a1[4] = { aF[1][0][2 * kk], aF[1][1][2 * kk],
                               aF[1][0][2 * kk + 1], aF[1][1][2 * kk + 1] };
#pragma unroll
            for (int np = 0; np < 4; np++) {
                unsigned bb4[4];
                ldsm_x4(bb4, bB + (uint32_t)((nbase + np * 16 + bRow) * 72 + k0 + bKh) * 2);
                mma_bf16(acc[0][2 * np],     a0, bb4[0], bb4[1]);
                mma_bf16(acc[1][2 * np],     a1, bb4[0], bb4[1]);
                mma_bf16(acc[0][2 * np + 1], a0, bb4[2], bb4[3]);
                mma_bf16(acc[1][2 * np + 1], a1, bb4[2], bb4[3]);
            }
        }
    }

    // epilogue: scale by 1/(rsum half0 + half1), write fp32 output
#pragma unroll
    for (int mt = 0; mt < 2; mt++) {
        const int r = mbase + mt * 16 + g;
        const int ridx = b * NF + q0 + r;
        const float ia = 1.f / (g_rsumH[ridx]     + g_rsumH[Bsz * NF + ridx]);
        const float ib = 1.f / (g_rsumH[ridx + 8] + g_rsumH[Bsz * NF + ridx + 8]);
        const size_t row0 = (size_t)(b * SEQ + q0 + r) * COUT;
        const size_t row1 = (size_t)(b * SEQ + q0 + r + 8) * COUT;
#pragma unroll
        for (int nt = 0; nt < 8; nt++) {
            const int col = nh * 128 + nbase + nt * 8 + 2 * t;
            *reinterpret_cast<float2*>(&out[row0 + col]) =
                make_float2(acc[mt][nt][0] * ia, acc[mt][nt][1] * ia);
            *reinterpret_cast<float2*>(&out[row1 + col]) =
                make_float2(acc[mt][nt][2] * ib, acc[mt][nt][3] * ib);
        }
    }
}

// ---------------- launch ----------------------------------------------------
extern "C" void kernel_launch(void* const* d_in, const int* in_sizes, int n_in,
                              void* d_out, int out_size) {
    const float* feat = (const float*)d_in[0];
    // d_in[1] = keep_flag (unused; layout is deterministic)
    const float* Wq = (const float*)d_in[2];
    const float* bq = (const float*)d_in[3];
    const float* Wk = (const float*)d_in[4];
    const float* bk = (const float*)d_in[5];
    const float* Wv = (const float*)d_in[6];
    const float* bv = (const float*)d_in[7];
    float* out = (float*)d_out;

    cudaFuncSetAttribute(k_proj,  cudaFuncAttributeMaxDynamicSharedMemorySize, PROJ_SMEM);
    cudaFuncSetAttribute(k_score, cudaFuncAttributeMaxDynamicSharedMemorySize, SCORE_SMEM);
    cudaFuncSetAttribute(k_pv,    cudaFuncAttributeMaxDynamicSharedMemorySize, PV_SMEM);

    k_convert<<<320, 256>>>(Wq, Wk, Wv);
    k_proj<<<(Bsz * SEQ) / 256, 256, PROJ_SMEM>>>(feat, bq, bk, bv, out);
    k_score<<<Bsz * 16 * 2, 256, SCORE_SMEM>>>();
    k_pv<<<Bsz * 16 * 2, 256, PV_SMEM>>>(out);
}

// round 16
// speedup vs baseline: 1.1303x; 1.1303x over previous
#include <cuda_runtime.h>
#include <cuda_bf16.h>
#include <cstdint>

#define Bsz  8
#define NF   2048
#define NK   4096
#define CIN  256
#define CKQ  64
#define COUT 256
#define SEQ  (NF + NK)

// ---------------- scratch (__device__ globals; no allocations allowed) -----
__device__ __align__(16) __nv_bfloat16 g_Wq[CKQ * CIN];
__device__ __align__(16) __nv_bfloat16 g_Wkv[(CKQ + COUT) * CIN];
__device__ __align__(16) __nv_bfloat16 g_Q[Bsz * NF * CKQ];        // log2-domain scaled
__device__ __align__(16) __nv_bfloat16 g_K[Bsz * NK * CKQ];
__device__ __align__(16) __nv_bfloat16 g_Vt[Bsz * COUT * NK];      // [b][c][key]
// P warp-tiled: [b][qt][kt][rg(16)][jb(4)][lane(32)][e(4)] u32 — coalesced both sides
__device__ __align__(16) __nv_bfloat16 g_P[Bsz * NF * NK];         // 128 MB
__device__ __align__(16) float         g_rsumH[2 * Bsz * NF];      // per-kt-half row sums

// 1/sqrt(64) * log2(e): scores land directly in log2 domain -> ex2.approx
#define SCALE_Q 0.180336884f

// =================== helpers =============================================
__device__ __forceinline__ uint32_t smem_u32(const void* p) {
    uint32_t a;
    asm("{ .reg .u64 t; cvta.to.shared.u64 t, %1; cvt.u32.u64 %0, t; }" : "=r"(a) : "l"(p));
    return a;
}
__device__ __forceinline__ float ex2f(float x) {
    float y; asm("ex2.approx.ftz.f32 %0, %1;" : "=f"(y) : "f"(x)); return y;
}
__device__ __forceinline__ unsigned pack_bf2(float lo, float hi) {
    __nv_bfloat162 h = __floats2bfloat162_rn(lo, hi);
    return *reinterpret_cast<unsigned*>(&h);
}
__device__ __forceinline__ void cp16(uint32_t dst, const void* src) {
    asm volatile("cp.async.cg.shared.global [%0], [%1], 16;" :: "r"(dst), "l"(src) : "memory");
}
#define CP_COMMIT() asm volatile("cp.async.commit_group;" ::: "memory")
#define CP_WAIT(n)  asm volatile("cp.async.wait_group %0;" :: "n"(n) : "memory")

// ldmatrix x4: four 8x8 b16 tiles
__device__ __forceinline__ void ldsm_x4(unsigned r[4], uint32_t addr) {
    asm volatile("ldmatrix.sync.aligned.m8n8.x4.shared.b16 {%0,%1,%2,%3}, [%4];"
        : "=r"(r[0]), "=r"(r[1]), "=r"(r[2]), "=r"(r[3]) : "r"(addr));
}

// mma.sync m16n8k16 bf16 -> f32 (sm_80 baseline; family-portable)
__device__ __forceinline__ void mma_bf16(float c[4], const unsigned a[4], const unsigned b0, const unsigned b1) {
    asm volatile(
        "mma.sync.aligned.m16n8k16.row.col.f32.bf16.bf16.f32 "
        "{%0,%1,%2,%3}, {%4,%5,%6,%7}, {%8,%9}, {%0,%1,%2,%3};\n"
        : "+f"(c[0]), "+f"(c[1]), "+f"(c[2]), "+f"(c[3])
        : "r"(a[0]), "r"(a[1]), "r"(a[2]), "r"(a[3]), "r"(b0), "r"(b1));
}
__device__ __forceinline__ void mma_bf16a(float c[4], const unsigned a[4], const unsigned b[2]) {
    mma_bf16(c, a, b[0], b[1]);
}

// ---------------- kernel 0: weight conversion ------------------------------
__global__ void k_convert(const float* __restrict__ Wq, const float* __restrict__ Wk,
                          const float* __restrict__ Wv) {
    int i = blockIdx.x * blockDim.x + threadIdx.x;
    const int n1 = CKQ * CIN;
    const int n2 = (CKQ + COUT) * CIN;
    if (i < n1) g_Wq[i] = __float2bfloat16_rn(Wq[i]);
    if (i < n2) g_Wkv[i] = __float2bfloat16_rn(i < n1 ? Wk[i] : Wv[i - n1]);
}

// ---------------- kernel 1: fused QKV projection + keep-row copy -----------
// 256-row tile per CTA (grid 192), 8 warps x M32. (Unchanged.)
#define AS_STRIDE 264
#define VS_STRIDE 66
#define PROJ_SMEM (256 * AS_STRIDE * 2 + 256 * VS_STRIDE * 2)   // 168960

__global__ __launch_bounds__(256) void k_proj(const float* __restrict__ feat,
                                              const float* __restrict__ bq,
                                              const float* __restrict__ bk,
                                              const float* __restrict__ bv,
                                              float* __restrict__ out) {
    extern __shared__ char smem[];
    __nv_bfloat16* As  = reinterpret_cast<__nv_bfloat16*>(smem);
    __nv_bfloat16* Vsm = reinterpret_cast<__nv_bfloat16*>(smem + 256 * AS_STRIDE * 2);

    const int tid = threadIdx.x;
    const int w = tid >> 5, lane = tid & 31;
    const int g = lane >> 2, t = lane & 3;
    const int m0 = w * 32;

    const int row0 = blockIdx.x * 256;
    const int b = row0 / SEQ;
    const int pos0 = row0 % SEQ;
    const bool is_fill = pos0 < NF;

    if (!is_fill) {
        const float4* src = reinterpret_cast<const float4*>(feat + (size_t)row0 * CIN);
        float4* dst = reinterpret_cast<float4*>(out + (size_t)row0 * CIN);
        for (int i = tid; i < 256 * CIN / 4; i += 256) dst[i] = src[i];
    }

    for (int i = tid; i < 256 * 64; i += 256) {
        const int r = i >> 6, c4 = i & 63;
        float4 v = *reinterpret_cast<const float4*>(&feat[(size_t)(row0 + r) * CIN + c4 * 4]);
        *reinterpret_cast<__nv_bfloat162*>(&As[r * AS_STRIDE + c4 * 4]) = __floats2bfloat162_rn(v.x, v.y);
        *reinterpret_cast<__nv_bfloat162*>(&As[r * AS_STRIDE + c4 * 4 + 2]) = __floats2bfloat162_rn(v.z, v.w);
    }
    __syncthreads();

    const int nchunks = is_fill ? 1 : 5;
    for (int nc = 0; nc < nchunks; nc++) {
        const __nv_bfloat16* W = is_fill ? g_Wq : g_Wkv;
        const int nbase = is_fill ? 0 : nc * 64;

        float acc[2][8][4];
#pragma unroll
        for (int mt = 0; mt < 2; mt++)
#pragma unroll
            for (int nt = 0; nt < 8; nt++) {
                acc[mt][nt][0] = acc[mt][nt][1] = acc[mt][nt][2] = acc[mt][nt][3] = 0.f;
            }

#pragma unroll
        for (int kt = 0; kt < 16; kt++) {
            const int k0 = kt * 16;
            unsigned a[2][4];
#pragma unroll
            for (int mt = 0; mt < 2; mt++) {
                const int r0 = m0 + mt * 16 + g;
                a[mt][0] = *reinterpret_cast<const unsigned*>(&As[r0       * AS_STRIDE + k0 + 2 * t]);
                a[mt][1] = *reinterpret_cast<const unsigned*>(&As[(r0 + 8) * AS_STRIDE + k0 + 2 * t]);
                a[mt][2] = *reinterpret_cast<const unsigned*>(&As[r0       * AS_STRIDE + k0 + 8 + 2 * t]);
                a[mt][3] = *reinterpret_cast<const unsigned*>(&As[(r0 + 8) * AS_STRIDE + k0 + 8 + 2 * t]);
            }
#pragma unroll
            for (int nt = 0; nt < 8; nt++) {
                const int n = nbase + nt * 8 + g;
                unsigned bf[2];
                bf[0] = *reinterpret_cast<const unsigned*>(&W[n * CIN + k0 + 2 * t]);
                bf[1] = *reinterpret_cast<const unsigned*>(&W[n * CIN + k0 + 8 + 2 * t]);
                mma_bf16a(acc[0][nt], a[0], bf);
                mma_bf16a(acc[1][nt], a[1], bf);
            }
        }

        if (is_fill) {
#pragma unroll
            for (int mt = 0; mt < 2; mt++) {
                const int qrow = b * NF + pos0 + m0 + mt * 16 + g;
#pragma unroll
                for (int nt = 0; nt < 8; nt++) {
                    const int col = nt * 8 + 2 * t;
                    const float b0v = bq[col], b1v = bq[col + 1];
                    *reinterpret_cast<unsigned*>(&g_Q[(size_t)qrow * CKQ + col]) =
                        pack_bf2((acc[mt][nt][0] + b0v) * SCALE_Q, (acc[mt][nt][1] + b1v) * SCALE_Q);
                    *reinterpret_cast<unsigned*>(&g_Q[(size_t)(qrow + 8) * CKQ + col]) =
                        pack_bf2((acc[mt][nt][2] + b0v) * SCALE_Q, (acc[mt][nt][3] + b1v) * SCALE_Q);
                }
            }
        } else if (nc == 0) {
#pragma unroll
            for (int mt = 0; mt < 2; mt++) {
                const int krow = b * NK + (pos0 - NF) + m0 + mt * 16 + g;
#pragma unroll
                for (int nt = 0; nt < 8; nt++) {
                    const int col = nt * 8 + 2 * t;
                    const float b0v = bk[col], b1v = bk[col + 1];
                    *reinterpret_cast<unsigned*>(&g_K[(size_t)krow * CKQ + col]) =
                        pack_bf2(acc[mt][nt][0] + b0v, acc[mt][nt][1] + b1v);
                    *reinterpret_cast<unsigned*>(&g_K[(size_t)(krow + 8) * CKQ + col]) =
                        pack_bf2(acc[mt][nt][2] + b0v, acc[mt][nt][3] + b1v);
                }
            }
        } else {
#pragma unroll
            for (int mt = 0; mt < 2; mt++) {
                const int r0 = m0 + mt * 16 + g;
#pragma unroll
                for (int nt = 0; nt < 8; nt++) {
                    const int col = nt * 8 + 2 * t;
                    const int nglob = (nc - 1) * 64 + col;
                    const float b0v = bv[nglob], b1v = bv[nglob + 1];
                    *reinterpret_cast<unsigned*>(&Vsm[r0       * VS_STRIDE + col]) =
                        pack_bf2(acc[mt][nt][0] + b0v, acc[mt][nt][1] + b1v);
                    *reinterpret_cast<unsigned*>(&Vsm[(r0 + 8) * VS_STRIDE + col]) =
                        pack_bf2(acc[mt][nt][2] + b0v, acc[mt][nt][3] + b1v);
                }
            }
            __syncthreads();
            const int key0 = pos0 - NF;
            for (int i = tid; i < 64 * 128; i += 256) {
                const int n = i >> 7;
                const int kp = i & 127;
                __nv_bfloat162 h;
                h.x = Vsm[(2 * kp)     * VS_STRIDE + n];
                h.y = Vsm[(2 * kp + 1) * VS_STRIDE + n];
                const int nglob = (nc - 1) * 64 + n;
                *reinterpret_cast<__nv_bfloat162*>(
                    &g_Vt[((size_t)(b * COUT + nglob)) * NK + key0 + 2 * kp]) = h;
            }
            __syncthreads();
        }
    }
}

// ---------------- kernel 2: scores + exp -> unnormalized P -----------------
// Each CTA: 128 q rows x HALF the KV range (16 tiles). grid = 256.
// 4-stage/1-barrier cp.async pipeline; P stored warp-tiled, fully coalesced.
#define SC_QS 72
#define SC_KS 72
#define SC_SMK(s) (18432 + (s) * 18432)
#define SCORE_SMEM (5 * 18432)     // Q + 4 K stages = 92160

__global__ __launch_bounds__(256, 2) void k_score() {
    extern __shared__ char smem[];
    const uint32_t sb = smem_u32(smem);
    const int tid = threadIdx.x;
    const int w = tid >> 5, lane = tid & 31;
    const int g = lane >> 2, t = lane & 3;
    const int m0 = w * 16;
    const int b  = blockIdx.x >> 5;
    const int qt = (blockIdx.x >> 1) & 15;
    const int h  = blockIdx.x & 1;
    const int q0 = qt * 128;
    const int kt0 = h * 16;

    const int bRow = (lane & 7) + ((lane >> 4) & 1) * 8;
    const int bKh  = ((lane >> 3) & 1) * 8;

    const __nv_bfloat16* gK = &g_K[(size_t)(b * NK) * CKQ];

    // stage Q tile
    for (int i = tid; i < 128 * 8; i += 256) {
        const int r = i >> 3, c4 = i & 7;
        const uint4 v = *reinterpret_cast<const uint4*>(
            &g_Q[((size_t)(b * NF + q0 + r)) * CKQ + c4 * 8]);
        *reinterpret_cast<uint4*>(smem + (r * SC_QS + c4 * 8) * 2) = v;
    }

    // prefetch K tiles kt0 .. kt0+2 into stages 0..2
#pragma unroll
    for (int pre = 0; pre < 3; pre++) {
        const uint32_t kb = sb + SC_SMK(pre);
        for (int i = tid; i < 1024; i += 256) {
            const int r = i >> 3, c = i & 7;
            cp16(kb + (r * SC_KS + c * 8) * 2, gK + (size_t)((kt0 + pre) * 128 + r) * CKQ + c * 8);
        }
        CP_COMMIT();
    }
    __syncthreads();

    const __nv_bfloat16* Qs = reinterpret_cast<const __nv_bfloat16*>(smem);
    unsigned qf[4][4];
#pragma unroll
    for (int j = 0; j < 4; j++) {
        const int k0 = j * 16;
        qf[j][0] = *reinterpret_cast<const unsigned*>(&Qs[(m0 + g)     * SC_QS + k0 + 2 * t]);
        qf[j][1] = *reinterpret_cast<const unsigned*>(&Qs[(m0 + g + 8) * SC_QS + k0 + 2 * t]);
        qf[j][2] = *reinterpret_cast<const unsigned*>(&Qs[(m0 + g)     * SC_QS + k0 + 8 + 2 * t]);
        qf[j][3] = *reinterpret_cast<const unsigned*>(&Qs[(m0 + g + 8) * SC_QS + k0 + 8 + 2 * t]);
    }

    float rsum0 = 0.f, rsum1 = 0.f;
    uint32_t* pbase = reinterpret_cast<uint32_t*>(g_P) + ((size_t)(b * 16 + qt)) * 32 * 8192;
    const int laneoff = lane * 4;            // (g*4 + t)*4

    for (int i = 0; i < 16; i++) {
        const int kt = kt0 + i;
        const int s = i & 3;
        const uint32_t ksb = sb + SC_SMK(s);

        CP_WAIT(2);
        __syncthreads();

        // prefetch tile kt+3 into stage (i+3)&3 (its reads finished at i-1)
        if (i + 3 < 16) {
            const uint32_t nb = sb + SC_SMK((i + 3) & 3);
            for (int ii = tid; ii < 1024; ii += 256) {
                const int r = ii >> 3, c = ii & 7;
                cp16(nb + (r * SC_KS + c * 8) * 2, gK + (size_t)((kt + 3) * 128 + r) * CKQ + c * 8);
            }
        }
        CP_COMMIT();

        float sv[16][4];
#pragma unroll
        for (int nt = 0; nt < 16; nt++) { sv[nt][0] = sv[nt][1] = sv[nt][2] = sv[nt][3] = 0.f; }
#pragma unroll
        for (int j = 0; j < 4; j++) {
            const int k0 = j * 16;
#pragma unroll
            for (int np = 0; np < 8; np++) {
                unsigned bb[4];
                ldsm_x4(bb, ksb + (uint32_t)((np * 16 + bRow) * SC_KS + k0 + bKh) * 2);
                mma_bf16(sv[2 * np],     qf[j], bb[0], bb[1]);
                mma_bf16(sv[2 * np + 1], qf[j], bb[2], bb[3]);
            }
        }

        // exp (log2 domain), row sums; store warp-tiled:
        // u32 idx = ((rg*4 + jb)*32 + lane)*4 + e, rg = row>>3, nt = 4*jb + e
        uint32_t* pb = pbase + (size_t)kt * 8192;
#pragma unroll
        for (int j = 0; j < 4; j++) {
            uint32_t w0[4], w1[4];
#pragma unroll
            for (int e = 0; e < 4; e++) {
                const int nt = 4 * j + e;
                const float p0 = ex2f(sv[nt][0]);
                const float p1 = ex2f(sv[nt][1]);
                const float p2 = ex2f(sv[nt][2]);
                const float p3 = ex2f(sv[nt][3]);
                rsum0 += p0 + p1;
                rsum1 += p2 + p3;
                w0[e] = pack_bf2(p0, p1);
                w1[e] = pack_bf2(p2, p3);
            }
            // rows m0+g  -> rg0 = w*2   -> block (w*8 + j)
            // rows m0+8+g-> rg1 = w*2+1 -> block (w*8 + 4 + j)
            *reinterpret_cast<uint4*>(&pb[(w * 8 + j) * 128 + laneoff]) =
                *reinterpret_cast<const uint4*>(w0);
            *reinterpret_cast<uint4*>(&pb[(w * 8 + 4 + j) * 128 + laneoff]) =
                *reinterpret_cast<const uint4*>(w1);
        }
    }

    // quad-reduce partial row sums, lane t==0 writes this half's sums
    rsum0 += __shfl_xor_sync(0xffffffffu, rsum0, 1);
    rsum0 += __shfl_xor_sync(0xffffffffu, rsum0, 2);
    rsum1 += __shfl_xor_sync(0xffffffffu, rsum1, 1);
    rsum1 += __shfl_xor_sync(0xffffffffu, rsum1, 2);
    if (t == 0) {
        g_rsumH[h * (Bsz * NF) + b * NF + q0 + m0 + g]     = rsum0;
        g_rsumH[h * (Bsz * NF) + b * NF + q0 + m0 + g + 8] = rsum1;
    }
}

// ---------------- kernel 3: O = P @ V, scaled by 1/rsum --------------------
// CTA: 128 q x 128 out channels, 8 warps (4M x 2N), M32N64/warp.
// A (P) loaded via fully-coalesced LDG.128 from warp-tiled P (no A smem).
// B (V) via 4-stage/1-barrier cp.async + ldmatrix. K-step 64.
#define PV_BST 18432                      // one B stage: 128 rows x 144B
#define PV_SMEM (4 * PV_BST)              // 73728

__global__ __launch_bounds__(256, 2) void k_pv(float* __restrict__ out) {
    extern __shared__ char smem[];
    const uint32_t sb = smem_u32(smem);
    const int tid = threadIdx.x;
    const int w = tid >> 5, lane = tid & 31;
    const int g = lane >> 2, t = lane & 3;
    const int mw = w & 3, nw = w >> 2;          // 4 x 2 warp grid
    const int mbase = mw * 32, nbase = nw * 64;

    const int bRow = (lane & 7) + ((lane >> 4) & 1) * 8;
    const int bKh  = ((lane >> 3) & 1) * 8;

    const int b  = blockIdx.x >> 5;
    const int qt = (blockIdx.x >> 1) & 15;
    const int nh = blockIdx.x & 1;
    const int q0 = qt * 128;

    const uint32_t* gPu = reinterpret_cast<const uint32_t*>(g_P) + ((size_t)(b * 16 + qt)) * 32 * 8192;
    const __nv_bfloat16* gV = &g_Vt[((size_t)(b * COUT + nh * 128)) * NK];

    // prefetch B (V) for ks = 0..2 into stages 0..2
#pragma unroll
    for (int pre = 0; pre < 3; pre++) {
        const uint32_t bb = sb + pre * PV_BST;
        for (int i = tid; i < 1024; i += 256) {
            const int r = i >> 3, c = i & 7;
            cp16(bb + r * 144 + c * 16, gV + (size_t)r * NK + pre * 64 + c * 8);
        }
        CP_COMMIT();
    }

    float acc[2][8][4];
#pragma unroll
    for (int mt = 0; mt < 2; mt++)
#pragma unroll
        for (int nt = 0; nt < 8; nt++) {
            acc[mt][nt][0] = acc[mt][nt][1] = acc[mt][nt][2] = acc[mt][nt][3] = 0.f;
        }

    for (int ks = 0; ks < 64; ks++) {           // 64 K-steps of 64 keys
        const int s = ks & 3;
        const int kt = ks >> 1, half = ks & 1;

        // A fragments: coalesced LDG.128 from warp-tiled P (32 lanes = one
        // contiguous 512B block per load). Issued before the wait/barrier.
        unsigned aF[2][2][8];
        const uint32_t* pA = gPu + (size_t)kt * 8192;
#pragma unroll
        for (int mt = 0; mt < 2; mt++) {
            const int rgA = mw * 4 + mt * 2;            // (mbase + mt*16) >> 3
            const uint32_t* p0 = pA + (rgA * 4 + 2 * half) * 128 + lane * 4;
            *reinterpret_cast<uint4*>(&aF[mt][0][0]) = *reinterpret_cast<const uint4*>(p0);
            *reinterpret_cast<uint4*>(&aF[mt][0][4]) = *reinterpret_cast<const uint4*>(p0 + 128);
            *reinterpret_cast<uint4*>(&aF[mt][1][0]) = *reinterpret_cast<const uint4*>(p0 + 512);
            *reinterpret_cast<uint4*>(&aF[mt][1][4]) = *reinterpret_cast<const uint4*>(p0 + 640);
        }

        CP_WAIT(2);
        __syncthreads();

        // prefetch B for ks+3 into stage (ks+3)&3 (reads finished at ks-1)
        if (ks + 3 < 64) {
            const int tn = ks + 3;
            const uint32_t bb = sb + ((ks + 3) & 3) * PV_BST;
            for (int i = tid; i < 1024; i += 256) {
                const int r = i >> 3, c = i & 7;
                cp16(bb + r * 144 + c * 16, gV + (size_t)r * NK + tn * 64 + c * 8);
            }
        }
        CP_COMMIT();

        const uint32_t bB = sb + s * PV_BST;
#pragma unroll
        for (int kk = 0; kk < 4; kk++) {
            const int k0 = kk * 16;
            unsigned a0[4] = { aF[0][0][2 * kk], aF[0][1][2 * kk],
                               aF[0][0][2 * kk + 1], aF[0][1][2 * kk + 1] };
            unsigned a1[4] = { aF[1][0][2 * kk], aF[1][1][2 * kk],
                               aF[1][0][2 * kk + 1], aF[1][1][2 * kk + 1] };
#pragma unroll
            for (int np = 0; np < 4; np++) {
                unsigned bb4[4];
                ldsm_x4(bb4, bB + (uint32_t)((nbase + np * 16 + bRow) * 72 + k0 + bKh) * 2);
                mma_bf16(acc[0][2 * np],     a0, bb4[0], bb4[1]);
                mma_bf16(acc[1][2 * np],     a1, bb4[0], bb4[1]);
                mma_bf16(acc[0][2 * np + 1], a0, bb4[2], bb4[3]);
                mma_bf16(acc[1][2 * np + 1], a1, bb4[2], bb4[3]);
            }
        }
    }

    // epilogue: scale by 1/(rsum half0 + half1), write fp32 output
#pragma unroll
    for (int mt = 0; mt < 2; mt++) {
        const int r = mbase + mt * 16 + g;
        const int ridx = b * NF + q0 + r;
        const float ia = 1.f / (g_rsumH[ridx]     + g_rsumH[Bsz * NF + ridx]);
        const float ib = 1.f / (g_rsumH[ridx + 8] + g_rsumH[Bsz * NF + ridx + 8]);
        const size_t row0 = (size_t)(b * SEQ + q0 + r) * COUT;
        const size_t row1 = (size_t)(b * SEQ + q0 + r + 8) * COUT;
#pragma unroll
        for (int nt = 0; nt < 8; nt++) {
            const int col = nh * 128 + nbase + nt * 8 + 2 * t;
            *reinterpret_cast<float2*>(&out[row0 + col]) =
                make_float2(acc[mt][nt][0] * ia, acc[mt][nt][1] * ia);
            *reinterpret_cast<float2*>(&out[row1 + col]) =
                make_float2(acc[mt][nt][2] * ib, acc[mt][nt][3] * ib);
        }
    }
}

// ---------------- launch ----------------------------------------------------
extern "C" void kernel_launch(void* const* d_in, const int* in_sizes, int n_in,
                              void* d_out, int out_size) {
    const float* feat = (const float*)d_in[0];
    // d_in[1] = keep_flag (unused; layout is deterministic)
    const float* Wq = (const float*)d_in[2];
    const float* bq = (const float*)d_in[3];
    const float* Wk = (const float*)d_in[4];
    const float* bk = (const float*)d_in[5];
    const float* Wv = (const float*)d_in[6];
    const float* bv = (const float*)d_in[7];
    float* out = (float*)d_out;

    cudaFuncSetAttribute(k_proj,  cudaFuncAttributeMaxDynamicSharedMemorySize, PROJ_SMEM);
    cudaFuncSetAttribute(k_score, cudaFuncAttributeMaxDynamicSharedMemorySize, SCORE_SMEM);
    cudaFuncSetAttribute(k_pv,    cudaFuncAttributeMaxDynamicSharedMemorySize, PV_SMEM);

    k_convert<<<320, 256>>>(Wq, Wk, Wv);
    k_proj<<<(Bsz * SEQ) / 256, 256, PROJ_SMEM>>>(feat, bq, bk, bv, out);
    k_score<<<Bsz * 16 * 2, 256, SCORE_SMEM>>>();
    k_pv<<<Bsz * 16 * 2, 256, PV_SMEM>>>(out);
}